// round 1
// baseline (speedup 1.0000x reference)
#include <cuda_runtime.h>
#include <cuda_bf16.h>
#include <cstdint>

// Problem constants
#define NS 256      // S (sequence rows of MSA)
#define NR 256      // R (residues)
#define NC 256      // C (c_m)
#define NCZ 128     // Cz
#define NH 8        // heads
#define ND 32       // per-head dim
#define NM (NS*NR)  // 65536 rows of m
#define NHD (NH*ND) // 256

// Scratch (device globals; no runtime allocation allowed)
__device__ static float g_mln[(size_t)NM * NC];       // LN(m)
__device__ static float g_q  [(size_t)NM * NHD];
__device__ static float g_k  [(size_t)NM * NHD];
__device__ static float g_v  [(size_t)NM * NHD];
__device__ static float g_g  [(size_t)NM * NHD];      // sigmoid gate
__device__ static float g_og [(size_t)NM * NHD];      // o * g
__device__ static float g_bias[(size_t)NH * NR * NR]; // pair bias, layout [h][k][q]

// ---------------------------------------------------------------------------
// Kernel 1: LayerNorm over m rows (C=256). One warp per row, 8 rows/block.
// ---------------------------------------------------------------------------
__global__ __launch_bounds__(256) void ln_m_kernel(const float* __restrict__ m,
                                                   const float* __restrict__ w,
                                                   const float* __restrict__ b) {
    int warp = threadIdx.x >> 5;
    int lane = threadIdx.x & 31;
    int row = blockIdx.x * 8 + warp;
    const float* x = m + (size_t)row * NC;
    float v[8];
    float s = 0.f, sq = 0.f;
#pragma unroll
    for (int i = 0; i < 8; i++) {
        v[i] = x[lane + i * 32];
        s += v[i];
        sq += v[i] * v[i];
    }
#pragma unroll
    for (int o = 16; o > 0; o >>= 1) {
        s  += __shfl_xor_sync(0xffffffffu, s, o);
        sq += __shfl_xor_sync(0xffffffffu, sq, o);
    }
    float mu = s * (1.f / NC);
    float var = sq * (1.f / NC) - mu * mu;
    float rstd = rsqrtf(var + 1e-5f);
    float* y = g_mln + (size_t)row * NC;
#pragma unroll
    for (int i = 0; i < 8; i++) {
        int c = lane + i * 32;
        y[c] = (v[i] - mu) * rstd * w[c] + b[c];
    }
}

// ---------------------------------------------------------------------------
// Kernel 2: LN(z) then project with w_z[128,8] -> pair bias stored [h][k][q].
// One warp per z row (q,k). 8 rows/block.
// ---------------------------------------------------------------------------
__global__ __launch_bounds__(256) void ln_z_bias_kernel(const float* __restrict__ z,
                                                        const float* __restrict__ w,
                                                        const float* __restrict__ b,
                                                        const float* __restrict__ wz) {
    int warp = threadIdx.x >> 5;
    int lane = threadIdx.x & 31;
    int row = blockIdx.x * 8 + warp;     // row = q*NR + k
    const float* x = z + (size_t)row * NCZ;
    float v[4];
    float s = 0.f, sq = 0.f;
#pragma unroll
    for (int i = 0; i < 4; i++) {
        v[i] = x[lane + i * 32];
        s += v[i];
        sq += v[i] * v[i];
    }
#pragma unroll
    for (int o = 16; o > 0; o >>= 1) {
        s  += __shfl_xor_sync(0xffffffffu, s, o);
        sq += __shfl_xor_sync(0xffffffffu, sq, o);
    }
    float mu = s * (1.f / NCZ);
    float var = sq * (1.f / NCZ) - mu * mu;
    float rstd = rsqrtf(var + 1e-5f);
    float p[NH];
#pragma unroll
    for (int h = 0; h < NH; h++) p[h] = 0.f;
#pragma unroll
    for (int i = 0; i < 4; i++) {
        int c = lane + i * 32;
        float y = (v[i] - mu) * rstd * w[c] + b[c];
#pragma unroll
        for (int h = 0; h < NH; h++) p[h] += y * wz[c * NH + h];
    }
#pragma unroll
    for (int h = 0; h < NH; h++) {
#pragma unroll
        for (int o = 16; o > 0; o >>= 1) p[h] += __shfl_xor_sync(0xffffffffu, p[h], o);
    }
    int q = row >> 8;
    int k = row & 255;
    // select p[lane] without dynamic register indexing
    float outv = p[0];
#pragma unroll
    for (int h = 1; h < NH; h++) outv = (lane == h) ? p[h] : outv;
    if (lane < NH) g_bias[(size_t)lane * (NR * NR) + k * NR + q] = outv;
}

// ---------------------------------------------------------------------------
// Kernel 3: fused QKVG projection GEMM.
// A = g_mln [65536,256], B in {wq,wk,wv,wg} [256,256] row-major.
// blockIdx.y in [0,16): mat = y>>2, ntile = y&3 (64 cols each).
// Tile: BM=128, BN=64, BK=16. 256 threads, each computes 8x4.
// ---------------------------------------------------------------------------
__global__ __launch_bounds__(256) void qkvg_gemm_kernel(const float* __restrict__ wq,
                                                        const float* __restrict__ wk,
                                                        const float* __restrict__ wv,
                                                        const float* __restrict__ wg,
                                                        const float* __restrict__ bg) {
    int mat   = blockIdx.y >> 2;
    int ntile = blockIdx.y & 3;
    const float* B = (mat == 0) ? wq : (mat == 1) ? wk : (mat == 2) ? wv : wg;
    float* Cout    = (mat == 0) ? g_q : (mat == 1) ? g_k : (mat == 2) ? g_v : g_g;

    int m0 = blockIdx.x * 128;
    int n0 = ntile * 64;
    __shared__ float As[16][128];
    __shared__ float Bs[16][64];

    int tid = threadIdx.x;
    int tr = tid >> 4;        // 0..15 (row group of 8)
    int tc = tid & 15;        // 0..15 (col group of 4)
    int rowA = tid >> 2;      // 0..63
    int c4A  = tid & 3;       // 0..3
    int rowB = tid >> 4;      // 0..15
    int c4B  = tid & 15;      // 0..15

    float acc[8][4];
#pragma unroll
    for (int i = 0; i < 8; i++)
#pragma unroll
        for (int j = 0; j < 4; j++) acc[i][j] = 0.f;

    for (int k0 = 0; k0 < NC; k0 += 16) {
#pragma unroll
        for (int hh = 0; hh < 2; hh++) {
            int r = rowA + hh * 64;
            float4 a = *(const float4*)(g_mln + (size_t)(m0 + r) * NC + k0 + c4A * 4);
            As[c4A * 4 + 0][r] = a.x;
            As[c4A * 4 + 1][r] = a.y;
            As[c4A * 4 + 2][r] = a.z;
            As[c4A * 4 + 3][r] = a.w;
        }
        float4 bv = *(const float4*)(B + (size_t)(k0 + rowB) * NHD + n0 + c4B * 4);
        *(float4*)(&Bs[rowB][c4B * 4]) = bv;
        __syncthreads();
#pragma unroll
        for (int kk = 0; kk < 16; kk++) {
            float4 a0 = *(const float4*)&As[kk][tr * 8];
            float4 a1 = *(const float4*)&As[kk][tr * 8 + 4];
            float4 b4 = *(const float4*)&Bs[kk][tc * 4];
            float av[8] = {a0.x, a0.y, a0.z, a0.w, a1.x, a1.y, a1.z, a1.w};
            float bvv[4] = {b4.x, b4.y, b4.z, b4.w};
#pragma unroll
            for (int i = 0; i < 8; i++)
#pragma unroll
                for (int j = 0; j < 4; j++) acc[i][j] += av[i] * bvv[j];
        }
        __syncthreads();
    }

    if (mat == 0) {
        const float sc = 0.17677669529663687f; // 1/sqrt(32)
#pragma unroll
        for (int i = 0; i < 8; i++)
#pragma unroll
            for (int j = 0; j < 4; j++) acc[i][j] *= sc;
    } else if (mat == 3) {
#pragma unroll
        for (int j = 0; j < 4; j++) {
            float bgv = bg[n0 + tc * 4 + j];
#pragma unroll
            for (int i = 0; i < 8; i++) {
                float xv = acc[i][j] + bgv;
                acc[i][j] = 1.f / (1.f + __expf(-xv));
            }
        }
    }
#pragma unroll
    for (int i = 0; i < 8; i++) {
        float4 o4 = make_float4(acc[i][0], acc[i][1], acc[i][2], acc[i][3]);
        *(float4*)(Cout + (size_t)(m0 + tr * 8 + i) * NHD + n0 + tc * 4) = o4;
    }
}

// ---------------------------------------------------------------------------
// Kernel 4: attention. Grid (S, H). 256 threads, thread q = one query row.
// Online softmax over 2 chunks of 128 keys. Output fused with gate: og = o*g.
// ---------------------------------------------------------------------------
__global__ __launch_bounds__(256, 2) void attn_kernel(const float* __restrict__ mask) {
    int s = blockIdx.x;
    int h = blockIdx.y;
    int q = threadIdx.x;

    __shared__ float4 Ksh[128][8];
    __shared__ float4 Vsh[128][8];
    __shared__ float  msksh[NR];

    // per-thread query vector (already scaled by 1/sqrt(D) in projection)
    float4 qv[8];
    {
        const float4* qp = (const float4*)(g_q + ((size_t)(s * NR + q) * NHD + h * ND));
#pragma unroll
        for (int i = 0; i < 8; i++) qv[i] = qp[i];
    }
    msksh[q] = 1.0e9f * (mask[s * NR + q] - 1.0f);

    float acc[32];
#pragma unroll
    for (int i = 0; i < 32; i++) acc[i] = 0.f;
    float mmax = -1e30f;
    float l = 0.f;

    const float* bptr = g_bias + (size_t)h * (NR * NR) + q;  // bptr[k*NR] = bias[h][k][q]

    for (int k0 = 0; k0 < NR; k0 += 128) {
        __syncthreads();
#pragma unroll
        for (int i = 0; i < 4; i++) {
            int idx = threadIdx.x + i * 256;      // 0..1023
            int kr = idx >> 3, d4 = idx & 7;
            size_t goff = (size_t)(s * NR + k0 + kr) * NHD + h * ND + d4 * 4;
            Ksh[kr][d4] = *(const float4*)(g_k + goff);
            Vsh[kr][d4] = *(const float4*)(g_v + goff);
        }
        __syncthreads();

        float bnext = bptr[(k0) * NR];
#pragma unroll 2
        for (int j = 0; j < 128; j++) {
            float bcur = bnext;
            if (j < 127) bnext = bptr[(k0 + j + 1) * NR];
            float d0 = 0.f, d1 = 0.f, d2 = 0.f, d3 = 0.f;
#pragma unroll
            for (int i = 0; i < 8; i++) {
                float4 kv = Ksh[j][i];
                d0 += qv[i].x * kv.x;
                d1 += qv[i].y * kv.y;
                d2 += qv[i].z * kv.z;
                d3 += qv[i].w * kv.w;
            }
            float sc = (d0 + d1) + (d2 + d3) + msksh[k0 + j] + bcur;
            if (sc > mmax) {
                float corr = __expf(mmax - sc);
                l *= corr;
#pragma unroll
                for (int i = 0; i < 32; i++) acc[i] *= corr;
                mmax = sc;
            }
            float p = __expf(sc - mmax);
            l += p;
#pragma unroll
            for (int i = 0; i < 8; i++) {
                float4 vv = Vsh[j][i];
                acc[4 * i + 0] += p * vv.x;
                acc[4 * i + 1] += p * vv.y;
                acc[4 * i + 2] += p * vv.z;
                acc[4 * i + 3] += p * vv.w;
            }
        }
    }

    float inv = 1.f / l;
    size_t off = (size_t)(s * NR + q) * NHD + h * ND;
    const float4* gp = (const float4*)(g_g + off);
    float4* op = (float4*)(g_og + off);
#pragma unroll
    for (int i = 0; i < 8; i++) {
        float4 gv = gp[i];
        op[i] = make_float4(acc[4 * i + 0] * inv * gv.x,
                            acc[4 * i + 1] * inv * gv.y,
                            acc[4 * i + 2] * inv * gv.z,
                            acc[4 * i + 3] * inv * gv.w);
    }
}

// ---------------------------------------------------------------------------
// Kernel 5: output GEMM: out = g_og @ wo + bo. Same tiling as kernel 3.
// ---------------------------------------------------------------------------
__global__ __launch_bounds__(256) void out_gemm_kernel(const float* __restrict__ wo,
                                                       const float* __restrict__ bo,
                                                       float* __restrict__ out) {
    int m0 = blockIdx.x * 128;
    int n0 = blockIdx.y * 64;
    __shared__ float As[16][128];
    __shared__ float Bs[16][64];

    int tid = threadIdx.x;
    int tr = tid >> 4;
    int tc = tid & 15;
    int rowA = tid >> 2;
    int c4A  = tid & 3;
    int rowB = tid >> 4;
    int c4B  = tid & 15;

    float acc[8][4];
#pragma unroll
    for (int i = 0; i < 8; i++)
#pragma unroll
        for (int j = 0; j < 4; j++) acc[i][j] = 0.f;

    for (int k0 = 0; k0 < NHD; k0 += 16) {
#pragma unroll
        for (int hh = 0; hh < 2; hh++) {
            int r = rowA + hh * 64;
            float4 a = *(const float4*)(g_og + (size_t)(m0 + r) * NHD + k0 + c4A * 4);
            As[c4A * 4 + 0][r] = a.x;
            As[c4A * 4 + 1][r] = a.y;
            As[c4A * 4 + 2][r] = a.z;
            As[c4A * 4 + 3][r] = a.w;
        }
        float4 bv = *(const float4*)(wo + (size_t)(k0 + rowB) * NC + n0 + c4B * 4);
        *(float4*)(&Bs[rowB][c4B * 4]) = bv;
        __syncthreads();
#pragma unroll
        for (int kk = 0; kk < 16; kk++) {
            float4 a0 = *(const float4*)&As[kk][tr * 8];
            float4 a1 = *(const float4*)&As[kk][tr * 8 + 4];
            float4 b4 = *(const float4*)&Bs[kk][tc * 4];
            float av[8] = {a0.x, a0.y, a0.z, a0.w, a1.x, a1.y, a1.z, a1.w};
            float bvv[4] = {b4.x, b4.y, b4.z, b4.w};
#pragma unroll
            for (int i = 0; i < 8; i++)
#pragma unroll
                for (int j = 0; j < 4; j++) acc[i][j] += av[i] * bvv[j];
        }
        __syncthreads();
    }

#pragma unroll
    for (int j = 0; j < 4; j++) {
        float bov = bo[n0 + tc * 4 + j];
#pragma unroll
        for (int i = 0; i < 8; i++) acc[i][j] += bov;
    }
#pragma unroll
    for (int i = 0; i < 8; i++) {
        float4 o4 = make_float4(acc[i][0], acc[i][1], acc[i][2], acc[i][3]);
        *(float4*)(out + (size_t)(m0 + tr * 8 + i) * NC + n0 + tc * 4) = o4;
    }
}

// ---------------------------------------------------------------------------
// Launch
// Inputs (metadata order): m, z, mask, ln_m_w, ln_m_b, ln_z_w, ln_z_b, w_z,
//                          wq, wk, wv, wg, bg, wo, bo
// ---------------------------------------------------------------------------
extern "C" void kernel_launch(void* const* d_in, const int* in_sizes, int n_in,
                              void* d_out, int out_size) {
    const float* m      = (const float*)d_in[0];
    const float* z      = (const float*)d_in[1];
    const float* mask   = (const float*)d_in[2];
    const float* ln_m_w = (const float*)d_in[3];
    const float* ln_m_b = (const float*)d_in[4];
    const float* ln_z_w = (const float*)d_in[5];
    const float* ln_z_b = (const float*)d_in[6];
    const float* w_z    = (const float*)d_in[7];
    const float* wq     = (const float*)d_in[8];
    const float* wk     = (const float*)d_in[9];
    const float* wv     = (const float*)d_in[10];
    const float* wg     = (const float*)d_in[11];
    const float* bg     = (const float*)d_in[12];
    const float* wo     = (const float*)d_in[13];
    const float* bo     = (const float*)d_in[14];
    float* out = (float*)d_out;

    ln_m_kernel<<<NM / 8, 256>>>(m, ln_m_w, ln_m_b);
    ln_z_bias_kernel<<<(NR * NR) / 8, 256>>>(z, ln_z_w, ln_z_b, w_z);
    qkvg_gemm_kernel<<<dim3(NM / 128, 16), 256>>>(wq, wk, wv, wg, bg);
    attn_kernel<<<dim3(NS, NH), 256>>>(mask);
    out_gemm_kernel<<<dim3(NM / 128, NC / 64), 256>>>(wo, bo, out);
}

// round 3
// speedup vs baseline: 1.0022x; 1.0022x over previous
#include <cuda_runtime.h>
#include <cuda_bf16.h>
#include <cstdint>

// Problem constants
#define NS 256      // S (sequence rows of MSA)
#define NR 256      // R (residues)
#define NC 256      // C (c_m)
#define NCZ 128     // Cz
#define NH 8        // heads
#define ND 32       // per-head dim
#define NM (NS*NR)  // 65536 rows of m
#define NHD (NH*ND) // 256

// Scratch (device globals; no runtime allocation allowed)
__device__ static float g_mln[(size_t)NM * NC];       // LN(m)
__device__ static float g_q  [(size_t)NM * NHD];
__device__ static float g_k  [(size_t)NM * NHD];
__device__ static float g_v  [(size_t)NM * NHD];
__device__ static float g_g  [(size_t)NM * NHD];      // sigmoid gate
__device__ static float g_og [(size_t)NM * NHD];      // o * g
__device__ static float g_bias[(size_t)NH * NR * NR]; // pair bias, layout [h][k][q]

// ---------------------------------------------------------------------------
// Kernel 1: LayerNorm over m rows (C=256). One warp per row, 8 rows/block.
// ---------------------------------------------------------------------------
__global__ __launch_bounds__(256) void ln_m_kernel(const float* __restrict__ m,
                                                   const float* __restrict__ w,
                                                   const float* __restrict__ b) {
    int warp = threadIdx.x >> 5;
    int lane = threadIdx.x & 31;
    int row = blockIdx.x * 8 + warp;
    const float* x = m + (size_t)row * NC;
    float v[8];
    float s = 0.f, sq = 0.f;
#pragma unroll
    for (int i = 0; i < 8; i++) {
        v[i] = x[lane + i * 32];
        s += v[i];
        sq += v[i] * v[i];
    }
#pragma unroll
    for (int o = 16; o > 0; o >>= 1) {
        s  += __shfl_xor_sync(0xffffffffu, s, o);
        sq += __shfl_xor_sync(0xffffffffu, sq, o);
    }
    float mu = s * (1.f / NC);
    float var = sq * (1.f / NC) - mu * mu;
    float rstd = rsqrtf(var + 1e-5f);
    float* y = g_mln + (size_t)row * NC;
#pragma unroll
    for (int i = 0; i < 8; i++) {
        int c = lane + i * 32;
        y[c] = (v[i] - mu) * rstd * w[c] + b[c];
    }
}

// ---------------------------------------------------------------------------
// Kernel 2: LN(z) then project with w_z[128,8] -> pair bias stored [h][k][q].
// One warp per z row (q,k). 8 rows/block.
// ---------------------------------------------------------------------------
__global__ __launch_bounds__(256) void ln_z_bias_kernel(const float* __restrict__ z,
                                                        const float* __restrict__ w,
                                                        const float* __restrict__ b,
                                                        const float* __restrict__ wz) {
    int warp = threadIdx.x >> 5;
    int lane = threadIdx.x & 31;
    int row = blockIdx.x * 8 + warp;     // row = q*NR + k
    const float* x = z + (size_t)row * NCZ;
    float v[4];
    float s = 0.f, sq = 0.f;
#pragma unroll
    for (int i = 0; i < 4; i++) {
        v[i] = x[lane + i * 32];
        s += v[i];
        sq += v[i] * v[i];
    }
#pragma unroll
    for (int o = 16; o > 0; o >>= 1) {
        s  += __shfl_xor_sync(0xffffffffu, s, o);
        sq += __shfl_xor_sync(0xffffffffu, sq, o);
    }
    float mu = s * (1.f / NCZ);
    float var = sq * (1.f / NCZ) - mu * mu;
    float rstd = rsqrtf(var + 1e-5f);
    float p[NH];
#pragma unroll
    for (int h = 0; h < NH; h++) p[h] = 0.f;
#pragma unroll
    for (int i = 0; i < 4; i++) {
        int c = lane + i * 32;
        float y = (v[i] - mu) * rstd * w[c] + b[c];
#pragma unroll
        for (int h = 0; h < NH; h++) p[h] += y * wz[c * NH + h];
    }
#pragma unroll
    for (int h = 0; h < NH; h++) {
#pragma unroll
        for (int o = 16; o > 0; o >>= 1) p[h] += __shfl_xor_sync(0xffffffffu, p[h], o);
    }
    int q = row >> 8;
    int k = row & 255;
    // select p[lane] without dynamic register indexing
    float outv = p[0];
#pragma unroll
    for (int h = 1; h < NH; h++) outv = (lane == h) ? p[h] : outv;
    if (lane < NH) g_bias[(size_t)lane * (NR * NR) + k * NR + q] = outv;
}

// ---------------------------------------------------------------------------
// Kernel 3: fused QKVG projection GEMM.
// A = g_mln [65536,256], B in {wq,wk,wv,wg} [256,256] row-major.
// blockIdx.y in [0,16): mat = y>>2, ntile = y&3 (64 cols each).
// Tile: BM=128, BN=64, BK=16. 256 threads, each computes 8x4.
// ---------------------------------------------------------------------------
__global__ __launch_bounds__(256) void qkvg_gemm_kernel(const float* __restrict__ wq,
                                                        const float* __restrict__ wk,
                                                        const float* __restrict__ wv,
                                                        const float* __restrict__ wg,
                                                        const float* __restrict__ bg) {
    int mat   = blockIdx.y >> 2;
    int ntile = blockIdx.y & 3;
    const float* B = (mat == 0) ? wq : (mat == 1) ? wk : (mat == 2) ? wv : wg;
    float* Cout    = (mat == 0) ? g_q : (mat == 1) ? g_k : (mat == 2) ? g_v : g_g;

    int m0 = blockIdx.x * 128;
    int n0 = ntile * 64;
    __shared__ float As[16][128];
    __shared__ float Bs[16][64];

    int tid = threadIdx.x;
    int tr = tid >> 4;        // 0..15 (row group of 8)
    int tc = tid & 15;        // 0..15 (col group of 4)
    int rowA = tid >> 2;      // 0..63
    int c4A  = tid & 3;       // 0..3
    int rowB = tid >> 4;      // 0..15
    int c4B  = tid & 15;      // 0..15

    float acc[8][4];
#pragma unroll
    for (int i = 0; i < 8; i++)
#pragma unroll
        for (int j = 0; j < 4; j++) acc[i][j] = 0.f;

    for (int k0 = 0; k0 < NC; k0 += 16) {
#pragma unroll
        for (int hh = 0; hh < 2; hh++) {
            int r = rowA + hh * 64;
            float4 a = *(const float4*)(g_mln + (size_t)(m0 + r) * NC + k0 + c4A * 4);
            As[c4A * 4 + 0][r] = a.x;
            As[c4A * 4 + 1][r] = a.y;
            As[c4A * 4 + 2][r] = a.z;
            As[c4A * 4 + 3][r] = a.w;
        }
        float4 bv = *(const float4*)(B + (size_t)(k0 + rowB) * NHD + n0 + c4B * 4);
        *(float4*)(&Bs[rowB][c4B * 4]) = bv;
        __syncthreads();
#pragma unroll
        for (int kk = 0; kk < 16; kk++) {
            float4 a0 = *(const float4*)&As[kk][tr * 8];
            float4 a1 = *(const float4*)&As[kk][tr * 8 + 4];
            float4 b4 = *(const float4*)&Bs[kk][tc * 4];
            float av[8] = {a0.x, a0.y, a0.z, a0.w, a1.x, a1.y, a1.z, a1.w};
            float bvv[4] = {b4.x, b4.y, b4.z, b4.w};
#pragma unroll
            for (int i = 0; i < 8; i++)
#pragma unroll
                for (int j = 0; j < 4; j++) acc[i][j] += av[i] * bvv[j];
        }
        __syncthreads();
    }

    if (mat == 0) {
        const float sc = 0.17677669529663687f; // 1/sqrt(32)
#pragma unroll
        for (int i = 0; i < 8; i++)
#pragma unroll
            for (int j = 0; j < 4; j++) acc[i][j] *= sc;
    } else if (mat == 3) {
#pragma unroll
        for (int j = 0; j < 4; j++) {
            float bgv = bg[n0 + tc * 4 + j];
#pragma unroll
            for (int i = 0; i < 8; i++) {
                float xv = acc[i][j] + bgv;
                acc[i][j] = 1.f / (1.f + __expf(-xv));
            }
        }
    }
#pragma unroll
    for (int i = 0; i < 8; i++) {
        float4 o4 = make_float4(acc[i][0], acc[i][1], acc[i][2], acc[i][3]);
        *(float4*)(Cout + (size_t)(m0 + tr * 8 + i) * NHD + n0 + tc * 4) = o4;
    }
}

// ---------------------------------------------------------------------------
// Kernel 4: attention. Grid (S, H). 256 threads, thread q = one query row.
// Online softmax over 2 chunks of 128 keys. Output fused with gate: og = o*g.
// ---------------------------------------------------------------------------
__global__ __launch_bounds__(256, 2) void attn_kernel(const float* __restrict__ mask) {
    int s = blockIdx.x;
    int h = blockIdx.y;
    int q = threadIdx.x;

    __shared__ float4 Ksh[128][8];
    __shared__ float4 Vsh[128][8];
    __shared__ float  msksh[NR];

    // per-thread query vector (already scaled by 1/sqrt(D) in projection)
    float4 qv[8];
    {
        const float4* qp = (const float4*)(g_q + ((size_t)(s * NR + q) * NHD + h * ND));
#pragma unroll
        for (int i = 0; i < 8; i++) qv[i] = qp[i];
    }
    msksh[q] = 1.0e9f * (mask[s * NR + q] - 1.0f);

    float acc[32];
#pragma unroll
    for (int i = 0; i < 32; i++) acc[i] = 0.f;
    float mmax = -1e30f;
    float l = 0.f;

    const float* bptr = g_bias + (size_t)h * (NR * NR) + q;  // bptr[k*NR] = bias[h][k][q]

    for (int k0 = 0; k0 < NR; k0 += 128) {
        __syncthreads();
#pragma unroll
        for (int i = 0; i < 4; i++) {
            int idx = threadIdx.x + i * 256;      // 0..1023
            int kr = idx >> 3, d4 = idx & 7;
            size_t goff = (size_t)(s * NR + k0 + kr) * NHD + h * ND + d4 * 4;
            Ksh[kr][d4] = *(const float4*)(g_k + goff);
            Vsh[kr][d4] = *(const float4*)(g_v + goff);
        }
        __syncthreads();

        float bnext = bptr[(k0) * NR];
#pragma unroll 2
        for (int j = 0; j < 128; j++) {
            float bcur = bnext;
            if (j < 127) bnext = bptr[(k0 + j + 1) * NR];
            float d0 = 0.f, d1 = 0.f, d2 = 0.f, d3 = 0.f;
#pragma unroll
            for (int i = 0; i < 8; i++) {
                float4 kv = Ksh[j][i];
                d0 += qv[i].x * kv.x;
                d1 += qv[i].y * kv.y;
                d2 += qv[i].z * kv.z;
                d3 += qv[i].w * kv.w;
            }
            float sc = (d0 + d1) + (d2 + d3) + msksh[k0 + j] + bcur;
            if (sc > mmax) {
                float corr = __expf(mmax - sc);
                l *= corr;
#pragma unroll
                for (int i = 0; i < 32; i++) acc[i] *= corr;
                mmax = sc;
            }
            float p = __expf(sc - mmax);
            l += p;
#pragma unroll
            for (int i = 0; i < 8; i++) {
                float4 vv = Vsh[j][i];
                acc[4 * i + 0] += p * vv.x;
                acc[4 * i + 1] += p * vv.y;
                acc[4 * i + 2] += p * vv.z;
                acc[4 * i + 3] += p * vv.w;
            }
        }
    }

    float inv = 1.f / l;
    size_t off = (size_t)(s * NR + q) * NHD + h * ND;
    const float4* gp = (const float4*)(g_g + off);
    float4* op = (float4*)(g_og + off);
#pragma unroll
    for (int i = 0; i < 8; i++) {
        float4 gv = gp[i];
        op[i] = make_float4(acc[4 * i + 0] * inv * gv.x,
                            acc[4 * i + 1] * inv * gv.y,
                            acc[4 * i + 2] * inv * gv.z,
                            acc[4 * i + 3] * inv * gv.w);
    }
}

// ---------------------------------------------------------------------------
// Kernel 5: output GEMM: out = g_og @ wo + bo. Same tiling as kernel 3.
// ---------------------------------------------------------------------------
__global__ __launch_bounds__(256) void out_gemm_kernel(const float* __restrict__ wo,
                                                       const float* __restrict__ bo,
                                                       float* __restrict__ out) {
    int m0 = blockIdx.x * 128;
    int n0 = blockIdx.y * 64;
    __shared__ float As[16][128];
    __shared__ float Bs[16][64];

    int tid = threadIdx.x;
    int tr = tid >> 4;
    int tc = tid & 15;
    int rowA = tid >> 2;
    int c4A  = tid & 3;
    int rowB = tid >> 4;
    int c4B  = tid & 15;

    float acc[8][4];
#pragma unroll
    for (int i = 0; i < 8; i++)
#pragma unroll
        for (int j = 0; j < 4; j++) acc[i][j] = 0.f;

    for (int k0 = 0; k0 < NHD; k0 += 16) {
#pragma unroll
        for (int hh = 0; hh < 2; hh++) {
            int r = rowA + hh * 64;
            float4 a = *(const float4*)(g_og + (size_t)(m0 + r) * NHD + k0 + c4A * 4);
            As[c4A * 4 + 0][r] = a.x;
            As[c4A * 4 + 1][r] = a.y;
            As[c4A * 4 + 2][r] = a.z;
            As[c4A * 4 + 3][r] = a.w;
        }
        float4 bv = *(const float4*)(wo + (size_t)(k0 + rowB) * NC + n0 + c4B * 4);
        *(float4*)(&Bs[rowB][c4B * 4]) = bv;
        __syncthreads();
#pragma unroll
        for (int kk = 0; kk < 16; kk++) {
            float4 a0 = *(const float4*)&As[kk][tr * 8];
            float4 a1 = *(const float4*)&As[kk][tr * 8 + 4];
            float4 b4 = *(const float4*)&Bs[kk][tc * 4];
            float av[8] = {a0.x, a0.y, a0.z, a0.w, a1.x, a1.y, a1.z, a1.w};
            float bvv[4] = {b4.x, b4.y, b4.z, b4.w};
#pragma unroll
            for (int i = 0; i < 8; i++)
#pragma unroll
                for (int j = 0; j < 4; j++) acc[i][j] += av[i] * bvv[j];
        }
        __syncthreads();
    }

#pragma unroll
    for (int j = 0; j < 4; j++) {
        float bov = bo[n0 + tc * 4 + j];
#pragma unroll
        for (int i = 0; i < 8; i++) acc[i][j] += bov;
    }
#pragma unroll
    for (int i = 0; i < 8; i++) {
        float4 o4 = make_float4(acc[i][0], acc[i][1], acc[i][2], acc[i][3]);
        *(float4*)(out + (size_t)(m0 + tr * 8 + i) * NC + n0 + tc * 4) = o4;
    }
}

// ---------------------------------------------------------------------------
// Launch
// Inputs (metadata order): m, z, mask, ln_m_w, ln_m_b, ln_z_w, ln_z_b, w_z,
//                          wq, wk, wv, wg, bg, wo, bo
// ---------------------------------------------------------------------------
extern "C" void kernel_launch(void* const* d_in, const int* in_sizes, int n_in,
                              void* d_out, int out_size) {
    const float* m      = (const float*)d_in[0];
    const float* z      = (const float*)d_in[1];
    const float* mask   = (const float*)d_in[2];
    const float* ln_m_w = (const float*)d_in[3];
    const float* ln_m_b = (const float*)d_in[4];
    const float* ln_z_w = (const float*)d_in[5];
    const float* ln_z_b = (const float*)d_in[6];
    const float* w_z    = (const float*)d_in[7];
    const float* wq     = (const float*)d_in[8];
    const float* wk     = (const float*)d_in[9];
    const float* wv     = (const float*)d_in[10];
    const float* wg     = (const float*)d_in[11];
    const float* bg     = (const float*)d_in[12];
    const float* wo     = (const float*)d_in[13];
    const float* bo     = (const float*)d_in[14];
    float* out = (float*)d_out;

    ln_m_kernel<<<NM / 8, 256>>>(m, ln_m_w, ln_m_b);
    ln_z_bias_kernel<<<(NR * NR) / 8, 256>>>(z, ln_z_w, ln_z_b, w_z);
    qkvg_gemm_kernel<<<dim3(NM / 128, 16), 256>>>(wq, wk, wv, wg, bg);
    attn_kernel<<<dim3(NS, NH), 256>>>(mask);
    out_gemm_kernel<<<dim3(NM / 128, NC / 64), 256>>>(wo, bo, out);
}